// round 1
// baseline (speedup 1.0000x reference)
#include <cuda_runtime.h>
#include <cstdint>

// Problem constants (fixed by setup_inputs)
#define Bv 32
#define Lv 512
#define Dv 384
#define Kv 8192
#define Nv (Bv*Lv)            // 16384 rows

// Output layout: concatenated float32 tuple
// (quantized_st[N*D], indices[N], loss[1], new_cluster_size[K],
//  new_embed_sum[K*D], new_codebook[K*D])
#define OFF_Q    ((size_t)0)
#define OFF_IDX  ((size_t)Nv*Dv)
#define OFF_LOSS (OFF_IDX + (size_t)Nv)
#define OFF_NCS  (OFF_LOSS + 1)
#define OFF_NES  (OFF_NCS + (size_t)Kv)
#define OFF_NCB  (OFF_NES + (size_t)Kv*Dv)

// Scratch (static device globals: no allocation allowed)
__device__ unsigned long long g_pack[Nv];       // packed (ordered-score<<32 | col)
__device__ float g_counts[Kv];
__device__ float g_embed[(size_t)Kv*Dv];
__device__ float g_c2[Kv];
__device__ float g_sumsq;
__device__ float g_sum_ema;

// ---------------------------------------------------------------------------
// Kernel 0: zero/init scratch (must run every launch; graph replays it)
// ---------------------------------------------------------------------------
__global__ void vq_init_kernel() {
    int i = blockIdx.x * blockDim.x + threadIdx.x;
    int stride = gridDim.x * blockDim.x;
    for (size_t j = i; j < (size_t)Kv * Dv; j += stride) g_embed[j] = 0.f;
    for (int j = i; j < Kv; j += stride) g_counts[j] = 0.f;
    for (int j = i; j < Nv; j += stride) g_pack[j] = ~0ull;
    if (i == 0) { g_sumsq = 0.f; g_sum_ema = 0.f; }
}

// ---------------------------------------------------------------------------
// Kernel 1: codebook row squared norms
// ---------------------------------------------------------------------------
__global__ void vq_c2_kernel(const float* __restrict__ cb) {
    int k = blockIdx.x;
    int t = threadIdx.x;  // 128 threads
    const float* r = cb + (size_t)k * Dv;
    float s = 0.f;
#pragma unroll
    for (int u = 0; u < 3; ++u) { float v = r[t + u * 128]; s = fmaf(v, v, s); }
#pragma unroll
    for (int o = 16; o; o >>= 1) s += __shfl_down_sync(0xffffffffu, s, o);
    __shared__ float ws[4];
    if ((t & 31) == 0) ws[t >> 5] = s;
    __syncthreads();
    if (t == 0) g_c2[k] = ws[0] + ws[1] + ws[2] + ws[3];
}

// ---------------------------------------------------------------------------
// Kernel 2: sum of ema_cluster_size (for smoothing denominator)
// ---------------------------------------------------------------------------
__global__ void vq_sumema_kernel(const float* __restrict__ ema_cs) {
    int t = threadIdx.x;  // 256 threads
    float s = 0.f;
    for (int j = t; j < Kv; j += 256) s += ema_cs[j];
#pragma unroll
    for (int o = 16; o; o >>= 1) s += __shfl_down_sync(0xffffffffu, s, o);
    __shared__ float ws[8];
    if ((t & 31) == 0) ws[t >> 5] = s;
    __syncthreads();
    if (t == 0) {
        float r = 0.f;
#pragma unroll
        for (int w = 0; w < 8; ++w) r += ws[w];
        g_sum_ema = r;
    }
}

// ---------------------------------------------------------------------------
// Kernel 3: distance GEMM + argmin (f32x2 packed FMA, double-buffered smem)
// ---------------------------------------------------------------------------
#define TM 128
#define TN 128
#define TK 8
#define NCH (Dv / TK)          // 48 d-chunks
#define KSPLIT 16
#define KTILES ((Kv / KSPLIT) / TN)  // 4 k-tiles per block

__device__ __forceinline__ void fma2(unsigned long long& d,
                                     unsigned long long a,
                                     unsigned long long b) {
    asm("fma.rn.f32x2 %0, %1, %2, %0;" : "+l"(d) : "l"(a), "l"(b));
}

// order-preserving float->uint, packed with column (ties -> lowest col wins,
// matching argmin first-occurrence semantics)
__device__ __forceinline__ unsigned long long packsc(float s, unsigned col) {
    unsigned u = __float_as_uint(s);
    u ^= ((unsigned)(((int)u) >> 31)) | 0x80000000u;
    return ((unsigned long long)u << 32) | col;
}

__global__ void __launch_bounds__(256, 2)
vq_argmin_kernel(const float* __restrict__ z, const float* __restrict__ cb) {
    __shared__ float2 Asd[2][TK][TM + 2];  // A duplicated into both f32x2 lanes
    __shared__ float  Bs [2][TK][TN + 4];
    __shared__ unsigned long long rbest[TM];

    const int tid = threadIdx.x;
    const int tx = tid & 15, ty = tid >> 4;
    const int row0 = blockIdx.x * TM;
    const int kbase = blockIdx.y * (Kv / KSPLIT);

    if (tid < TM) rbest[tid] = ~0ull;

    // loader: each thread loads one float4 of A and one of B per chunk
    const int lr = tid >> 1;            // row within tile (0..127)
    const int lc = (tid & 1) * 4;       // d-offset within chunk (0 or 4)
    const float* zp  = z  + (size_t)(row0 + lr) * Dv + lc;
    const float* bp0 = cb + (size_t)(kbase + lr) * Dv + lc;

    auto do_load = [&](int buf, int kt, int ch) {
        const float4 av = *(const float4*)(zp + ch * TK);
        const float4 bv = *(const float4*)(bp0 + (size_t)kt * TN * Dv + ch * TK);
        Asd[buf][lc + 0][lr] = make_float2(av.x, av.x);
        Asd[buf][lc + 1][lr] = make_float2(av.y, av.y);
        Asd[buf][lc + 2][lr] = make_float2(av.z, av.z);
        Asd[buf][lc + 3][lr] = make_float2(av.w, av.w);
        Bs[buf][lc + 0][lr] = bv.x;
        Bs[buf][lc + 1][lr] = bv.y;
        Bs[buf][lc + 2][lr] = bv.z;
        Bs[buf][lc + 3][lr] = bv.w;
    };

    do_load(0, 0, 0);
    int buf = 0;

    for (int kt = 0; kt < KTILES; ++kt) {
        unsigned long long acc[8][4];
#pragma unroll
        for (int i = 0; i < 8; ++i)
#pragma unroll
            for (int j = 0; j < 4; ++j) acc[i][j] = 0ull;

        for (int ch = 0; ch < NCH; ++ch) {
            __syncthreads();
            int nkt = kt, nch = ch + 1;
            if (nch == NCH) { nch = 0; ++nkt; }
            if (nkt < KTILES) do_load(buf ^ 1, nkt, nch);

#pragma unroll
            for (int d = 0; d < TK; ++d) {
                unsigned long long av8[8];
                ((ulonglong2*)av8)[0] = *(const ulonglong2*)&Asd[buf][d][ty * 8 + 0];
                ((ulonglong2*)av8)[1] = *(const ulonglong2*)&Asd[buf][d][ty * 8 + 2];
                ((ulonglong2*)av8)[2] = *(const ulonglong2*)&Asd[buf][d][ty * 8 + 4];
                ((ulonglong2*)av8)[3] = *(const ulonglong2*)&Asd[buf][d][ty * 8 + 6];
                unsigned long long bv4[4];
                ((ulonglong2*)bv4)[0] = *(const ulonglong2*)&Bs[buf][d][tx * 8 + 0];
                ((ulonglong2*)bv4)[1] = *(const ulonglong2*)&Bs[buf][d][tx * 8 + 4];
#pragma unroll
                for (int i = 0; i < 8; ++i)
#pragma unroll
                    for (int j = 0; j < 4; ++j) fma2(acc[i][j], av8[i], bv4[j]);
            }
            buf ^= 1;
        }

        // tile epilogue: score = ||c||^2 - 2*dot ; packed min per row
        const unsigned colbase = (unsigned)(kbase + kt * TN + tx * 8);
        const float4 c2a = *(const float4*)&g_c2[colbase];
        const float4 c2b = *(const float4*)&g_c2[colbase + 4];
        const float c2v[8] = {c2a.x, c2a.y, c2a.z, c2a.w,
                              c2b.x, c2b.y, c2b.z, c2b.w};
#pragma unroll
        for (int i = 0; i < 8; ++i) {
            unsigned long long best = ~0ull;
#pragma unroll
            for (int j = 0; j < 4; ++j) {
                unsigned long long p = acc[i][j];
                float flo = __uint_as_float((unsigned)p);
                float fhi = __uint_as_float((unsigned)(p >> 32));
                unsigned long long plo =
                    packsc(fmaf(-2.f, flo, c2v[2 * j]), colbase + 2 * j);
                unsigned long long phi =
                    packsc(fmaf(-2.f, fhi, c2v[2 * j + 1]), colbase + 2 * j + 1);
                if (plo < best) best = plo;
                if (phi < best) best = phi;
            }
#pragma unroll
            for (int off = 8; off > 0; off >>= 1) {
                unsigned long long o = __shfl_xor_sync(0xffffffffu, best, off, 16);
                if (o < best) best = o;
            }
            if (tx == 0) {
                int rw = ty * 8 + i;
                if (best < rbest[rw]) rbest[rw] = best;
            }
        }
    }

    __syncthreads();
    if (tid < TM) atomicMin(&g_pack[row0 + tid], rbest[tid]);
}

// ---------------------------------------------------------------------------
// Kernel 4: gather quantized, straight-through output, loss partial, EMA scatter
// ---------------------------------------------------------------------------
__global__ void vq_gather_kernel(const float* __restrict__ z,
                                 const float* __restrict__ cb,
                                 float* __restrict__ out,
                                 long long out_size) {
    int n = blockIdx.x;
    int t = threadIdx.x;  // 128 threads
    int idx = (int)(g_pack[n] & 0xffffffffull);
    const float* zr = z + (size_t)n * Dv;
    const float* cr = cb + (size_t)idx * Dv;
    float ss = 0.f;
#pragma unroll
    for (int u = 0; u < 3; ++u) {
        int d = t + u * 128;
        float zv = zr[d];
        float q = cr[d];
        out[OFF_Q + (size_t)n * Dv + d] = zv + (q - zv);  // straight-through
        float df = zv - q;
        ss = fmaf(df, df, ss);
        atomicAdd(&g_embed[(size_t)idx * Dv + d], zv);
    }
#pragma unroll
    for (int o = 16; o; o >>= 1) ss += __shfl_down_sync(0xffffffffu, ss, o);
    __shared__ float ws[4];
    if ((t & 31) == 0) ws[t >> 5] = ss;
    __syncthreads();
    if (t == 0) {
        atomicAdd(&g_sumsq, ws[0] + ws[1] + ws[2] + ws[3]);
        atomicAdd(&g_counts[idx], 1.0f);
        if (out_size > (long long)OFF_IDX) out[OFF_IDX + n] = (float)idx;
    }
}

// ---------------------------------------------------------------------------
// Kernel 5: finalize EMA outputs + loss
// ---------------------------------------------------------------------------
__global__ void vq_finalize_kernel(const float* __restrict__ ema_cs,
                                   const float* __restrict__ ema_es,
                                   float* __restrict__ out,
                                   long long out_size) {
    int k = blockIdx.x;
    int t = threadIdx.x;  // 128 threads
    // n = sum(new_cluster_size) = 0.99*sum(ema) + 0.01*N (counts sum to N exactly)
    float nn = 0.99f * g_sum_ema + 0.01f * (float)Nv;
    float ncs = 0.99f * ema_cs[k] + 0.01f * g_counts[k];
    float smoothed = (ncs + 1e-5f) / (nn + (float)Kv * 1e-5f) * nn;
    if (t == 0 && out_size > (long long)OFF_NCS) out[OFF_NCS + k] = ncs;
    if (t == 0 && k == 0 && out_size > (long long)OFF_LOSS)
        out[OFF_LOSS] = 1.25f * g_sumsq / (float)((size_t)Nv * Dv);
    if (out_size > (long long)OFF_NES) {
#pragma unroll
        for (int u = 0; u < 3; ++u) {
            int d = t + u * 128;
            size_t o = (size_t)k * Dv + d;
            float nes = 0.99f * ema_es[o] + 0.01f * g_embed[o];
            out[OFF_NES + o] = nes;
            out[OFF_NCB + o] = nes / smoothed;
        }
    }
}

// ---------------------------------------------------------------------------
extern "C" void kernel_launch(void* const* d_in, const int* in_sizes, int n_in,
                              void* d_out, int out_size) {
    const float* z       = (const float*)d_in[0];
    const float* cb      = (const float*)d_in[1];
    const float* ema_cs  = (const float*)d_in[2];
    const float* ema_es  = (const float*)d_in[3];
    float* out = (float*)d_out;
    (void)in_sizes; (void)n_in;

    vq_init_kernel<<<2048, 256>>>();
    vq_c2_kernel<<<Kv, 128>>>(cb);
    vq_sumema_kernel<<<1, 256>>>(ema_cs);
    vq_argmin_kernel<<<dim3(Nv / TM, KSPLIT), 256>>>(z, cb);
    vq_gather_kernel<<<Nv, 128>>>(z, cb, out, (long long)out_size);
    vq_finalize_kernel<<<Kv, 128>>>(ema_cs, ema_es, out, (long long)out_size);
}

// round 2
// speedup vs baseline: 1.1541x; 1.1541x over previous
#include <cuda_runtime.h>
#include <cstdint>

// Problem constants (fixed by setup_inputs)
#define Bv 32
#define Lv 512
#define Dv 384
#define Kv 8192
#define Nv (Bv*Lv)            // 16384 rows

// Output layout: concatenated float32 tuple
#define OFF_Q    ((size_t)0)
#define OFF_IDX  ((size_t)Nv*Dv)
#define OFF_LOSS (OFF_IDX + (size_t)Nv)
#define OFF_NCS  (OFF_LOSS + 1)
#define OFF_NES  (OFF_NCS + (size_t)Kv)
#define OFF_NCB  (OFF_NES + (size_t)Kv*Dv)

// Scratch (static device globals: no allocation allowed)
__device__ unsigned long long g_pack[Nv];       // packed (ordered-score<<32 | col)
__device__ float g_counts[Kv];
__device__ float g_embed[(size_t)Kv*Dv];
__device__ float g_c2[Kv];
__device__ float g_sumsq;
__device__ float g_sum_ema;

// ---------------------------------------------------------------------------
// Kernel 0: zero/init scratch (must run every launch; graph replays it)
// ---------------------------------------------------------------------------
__global__ void vq_init_kernel() {
    int i = blockIdx.x * blockDim.x + threadIdx.x;
    int stride = gridDim.x * blockDim.x;
    for (size_t j = i; j < (size_t)Kv * Dv; j += stride) g_embed[j] = 0.f;
    for (int j = i; j < Kv; j += stride) g_counts[j] = 0.f;
    for (int j = i; j < Nv; j += stride) g_pack[j] = ~0ull;
    if (i == 0) { g_sumsq = 0.f; g_sum_ema = 0.f; }
}

// ---------------------------------------------------------------------------
// Kernel 1: codebook row squared norms
// ---------------------------------------------------------------------------
__global__ void vq_c2_kernel(const float* __restrict__ cb) {
    int k = blockIdx.x;
    int t = threadIdx.x;  // 128 threads
    const float* r = cb + (size_t)k * Dv;
    float s = 0.f;
#pragma unroll
    for (int u = 0; u < 3; ++u) { float v = r[t + u * 128]; s = fmaf(v, v, s); }
#pragma unroll
    for (int o = 16; o; o >>= 1) s += __shfl_down_sync(0xffffffffu, s, o);
    __shared__ float ws[4];
    if ((t & 31) == 0) ws[t >> 5] = s;
    __syncthreads();
    if (t == 0) g_c2[k] = ws[0] + ws[1] + ws[2] + ws[3];
}

// ---------------------------------------------------------------------------
// Kernel 2: sum of ema_cluster_size (for smoothing denominator)
// ---------------------------------------------------------------------------
__global__ void vq_sumema_kernel(const float* __restrict__ ema_cs) {
    int t = threadIdx.x;  // 256 threads
    float s = 0.f;
    for (int j = t; j < Kv; j += 256) s += ema_cs[j];
#pragma unroll
    for (int o = 16; o; o >>= 1) s += __shfl_down_sync(0xffffffffu, s, o);
    __shared__ float ws[8];
    if ((t & 31) == 0) ws[t >> 5] = s;
    __syncthreads();
    if (t == 0) {
        float r = 0.f;
#pragma unroll
        for (int w = 0; w < 8; ++w) r += ws[w];
        g_sum_ema = r;
    }
}

// ---------------------------------------------------------------------------
// Kernel 3: distance GEMM + argmin (f32x2 packed FMA, register-side A dup)
// ---------------------------------------------------------------------------
#define TM 128
#define TN 128
#define TK 8
#define NCH (Dv / TK)          // 48 d-chunks
#define KSPLIT 16
#define KTILES ((Kv / KSPLIT) / TN)  // 4 k-tiles per block

__device__ __forceinline__ void fma2(unsigned long long& d,
                                     unsigned long long a,
                                     unsigned long long b) {
    asm("fma.rn.f32x2 %0, %1, %2, %0;" : "+l"(d) : "l"(a), "l"(b));
}

// duplicate a float into both lanes of an f32x2 operand (1 MOV pair in SASS)
__device__ __forceinline__ unsigned long long dup2(float a) {
    unsigned long long r;
    asm("mov.b64 %0, {%1, %1};" : "=l"(r) : "f"(a));
    return r;
}

// order-preserving float->uint, packed with column (ties -> lowest col wins)
__device__ __forceinline__ unsigned long long packsc(float s, unsigned col) {
    unsigned u = __float_as_uint(s);
    u ^= ((unsigned)(((int)u) >> 31)) | 0x80000000u;
    return ((unsigned long long)u << 32) | col;
}

__global__ void __launch_bounds__(256, 2)
vq_argmin_kernel(const float* __restrict__ z, const float* __restrict__ cb) {
    __shared__ float As[2][TK][TM + 4];   // plain floats (no duplication)
    __shared__ float Bs[2][TK][TN + 4];
    __shared__ unsigned long long rbest[TM];

    const int tid = threadIdx.x;
    const int tx = tid & 15, ty = tid >> 4;
    const int row0 = blockIdx.x * TM;
    const int kbase = blockIdx.y * (Kv / KSPLIT);

    if (tid < TM) rbest[tid] = ~0ull;

    // loader: each thread loads one float4 of A and one of B per chunk
    const int lr = tid >> 1;            // row within tile (0..127)
    const int lc = (tid & 1) * 4;       // d-offset within chunk (0 or 4)
    const float* zp  = z  + (size_t)(row0 + lr) * Dv + lc;
    const float* bp0 = cb + (size_t)(kbase + lr) * Dv + lc;

    auto do_load = [&](int buf, int kt, int ch) {
        const float4 av = *(const float4*)(zp + ch * TK);
        const float4 bv = *(const float4*)(bp0 + (size_t)kt * TN * Dv + ch * TK);
        As[buf][lc + 0][lr] = av.x;
        As[buf][lc + 1][lr] = av.y;
        As[buf][lc + 2][lr] = av.z;
        As[buf][lc + 3][lr] = av.w;
        Bs[buf][lc + 0][lr] = bv.x;
        Bs[buf][lc + 1][lr] = bv.y;
        Bs[buf][lc + 2][lr] = bv.z;
        Bs[buf][lc + 3][lr] = bv.w;
    };

    do_load(0, 0, 0);
    int buf = 0;

    for (int kt = 0; kt < KTILES; ++kt) {
        unsigned long long acc[8][4];
#pragma unroll
        for (int i = 0; i < 8; ++i)
#pragma unroll
            for (int j = 0; j < 4; ++j) acc[i][j] = 0ull;

        for (int ch = 0; ch < NCH; ++ch) {
            __syncthreads();
            int nkt = kt, nch = ch + 1;
            if (nch == NCH) { nch = 0; ++nkt; }
            if (nkt < KTILES) do_load(buf ^ 1, nkt, nch);

#pragma unroll
            for (int d = 0; d < TK; ++d) {
                const float4 a0 = *(const float4*)&As[buf][d][ty * 8 + 0];
                const float4 a1 = *(const float4*)&As[buf][d][ty * 8 + 4];
                unsigned long long av8[8];
                av8[0] = dup2(a0.x); av8[1] = dup2(a0.y);
                av8[2] = dup2(a0.z); av8[3] = dup2(a0.w);
                av8[4] = dup2(a1.x); av8[5] = dup2(a1.y);
                av8[6] = dup2(a1.z); av8[7] = dup2(a1.w);
                unsigned long long bv4[4];
                ((ulonglong2*)bv4)[0] = *(const ulonglong2*)&Bs[buf][d][tx * 8 + 0];
                ((ulonglong2*)bv4)[1] = *(const ulonglong2*)&Bs[buf][d][tx * 8 + 4];
#pragma unroll
                for (int i = 0; i < 8; ++i)
#pragma unroll
                    for (int j = 0; j < 4; ++j) fma2(acc[i][j], av8[i], bv4[j]);
            }
            buf ^= 1;
        }

        // tile epilogue: score = ||c||^2 - 2*dot ; packed min per row
        const unsigned colbase = (unsigned)(kbase + kt * TN + tx * 8);
        const float4 c2a = *(const float4*)&g_c2[colbase];
        const float4 c2b = *(const float4*)&g_c2[colbase + 4];
        const float c2v[8] = {c2a.x, c2a.y, c2a.z, c2a.w,
                              c2b.x, c2b.y, c2b.z, c2b.w};
#pragma unroll
        for (int i = 0; i < 8; ++i) {
            unsigned long long best = ~0ull;
#pragma unroll
            for (int j = 0; j < 4; ++j) {
                unsigned long long p = acc[i][j];
                float flo = __uint_as_float((unsigned)p);
                float fhi = __uint_as_float((unsigned)(p >> 32));
                unsigned long long plo =
                    packsc(fmaf(-2.f, flo, c2v[2 * j]), colbase + 2 * j);
                unsigned long long phi =
                    packsc(fmaf(-2.f, fhi, c2v[2 * j + 1]), colbase + 2 * j + 1);
                if (plo < best) best = plo;
                if (phi < best) best = phi;
            }
#pragma unroll
            for (int off = 8; off > 0; off >>= 1) {
                unsigned long long o = __shfl_xor_sync(0xffffffffu, best, off, 16);
                if (o < best) best = o;
            }
            if (tx == 0) {
                int rw = ty * 8 + i;
                if (best < rbest[rw]) rbest[rw] = best;
            }
        }
    }

    __syncthreads();
    if (tid < TM) atomicMin(&g_pack[row0 + tid], rbest[tid]);
}

// ---------------------------------------------------------------------------
// Kernel 4: gather quantized, straight-through output, loss partial, EMA scatter
// ---------------------------------------------------------------------------
__global__ void vq_gather_kernel(const float* __restrict__ z,
                                 const float* __restrict__ cb,
                                 float* __restrict__ out,
                                 long long out_size) {
    int n = blockIdx.x;
    int t = threadIdx.x;  // 128 threads
    int idx = (int)(g_pack[n] & 0xffffffffull);
    const float* zr = z + (size_t)n * Dv;
    const float* cr = cb + (size_t)idx * Dv;
    float ss = 0.f;
#pragma unroll
    for (int u = 0; u < 3; ++u) {
        int d = t + u * 128;
        float zv = zr[d];
        float q = cr[d];
        out[OFF_Q + (size_t)n * Dv + d] = zv + (q - zv);  // straight-through
        float df = zv - q;
        ss = fmaf(df, df, ss);
        atomicAdd(&g_embed[(size_t)idx * Dv + d], zv);
    }
#pragma unroll
    for (int o = 16; o; o >>= 1) ss += __shfl_down_sync(0xffffffffu, ss, o);
    __shared__ float ws[4];
    if ((t & 31) == 0) ws[t >> 5] = ss;
    __syncthreads();
    if (t == 0) {
        atomicAdd(&g_sumsq, ws[0] + ws[1] + ws[2] + ws[3]);
        atomicAdd(&g_counts[idx], 1.0f);
        if (out_size > (long long)OFF_IDX) out[OFF_IDX + n] = (float)idx;
    }
}

// ---------------------------------------------------------------------------
// Kernel 5: finalize EMA outputs + loss
// ---------------------------------------------------------------------------
__global__ void vq_finalize_kernel(const float* __restrict__ ema_cs,
                                   const float* __restrict__ ema_es,
                                   float* __restrict__ out,
                                   long long out_size) {
    int k = blockIdx.x;
    int t = threadIdx.x;  // 128 threads
    float nn = 0.99f * g_sum_ema + 0.01f * (float)Nv;
    float ncs = 0.99f * ema_cs[k] + 0.01f * g_counts[k];
    float smoothed = (ncs + 1e-5f) / (nn + (float)Kv * 1e-5f) * nn;
    if (t == 0 && out_size > (long long)OFF_NCS) out[OFF_NCS + k] = ncs;
    if (t == 0 && k == 0 && out_size > (long long)OFF_LOSS)
        out[OFF_LOSS] = 1.25f * g_sumsq / (float)((size_t)Nv * Dv);
    if (out_size > (long long)OFF_NES) {
#pragma unroll
        for (int u = 0; u < 3; ++u) {
            int d = t + u * 128;
            size_t o = (size_t)k * Dv + d;
            float nes = 0.99f * ema_es[o] + 0.01f * g_embed[o];
            out[OFF_NES + o] = nes;
            out[OFF_NCB + o] = nes / smoothed;
        }
    }
}

// ---------------------------------------------------------------------------
extern "C" void kernel_launch(void* const* d_in, const int* in_sizes, int n_in,
                              void* d_out, int out_size) {
    const float* z       = (const float*)d_in[0];
    const float* cb      = (const float*)d_in[1];
    const float* ema_cs  = (const float*)d_in[2];
    const float* ema_es  = (const float*)d_in[3];
    float* out = (float*)d_out;
    (void)in_sizes; (void)n_in;

    vq_init_kernel<<<2048, 256>>>();
    vq_c2_kernel<<<Kv, 128>>>(cb);
    vq_sumema_kernel<<<1, 256>>>(ema_cs);
    vq_argmin_kernel<<<dim3(Nv / TM, KSPLIT), 256>>>(z, cb);
    vq_gather_kernel<<<Nv, 128>>>(z, cb, out, (long long)out_size);
    vq_finalize_kernel<<<Kv, 128>>>(ema_cs, ema_es, out, (long long)out_size);
}

// round 4
// speedup vs baseline: 1.3552x; 1.1743x over previous
#include <cuda_runtime.h>
#include <cstdint>

// Problem constants (fixed by setup_inputs)
#define Bv 32
#define Lv 512
#define Dv 384
#define Kv 8192
#define Nv (Bv*Lv)            // 16384 rows

// Output layout: concatenated float32 tuple
#define OFF_Q    ((size_t)0)
#define OFF_IDX  ((size_t)Nv*Dv)
#define OFF_LOSS (OFF_IDX + (size_t)Nv)
#define OFF_NCS  (OFF_LOSS + 1)
#define OFF_NES  (OFF_NCS + (size_t)Kv)
#define OFF_NCB  (OFF_NES + (size_t)Kv*Dv)

// Scratch (static device globals: no allocation allowed)
__device__ unsigned long long g_pack[Nv];
__device__ float g_counts[Kv];
__device__ float g_embed[(size_t)Kv*Dv];
__device__ float g_c2[Kv];
__device__ float g_sumsq;
__device__ float g_sum_ema;

// order-preserving pack (ties -> lowest col wins, matching argmin)
__device__ __forceinline__ unsigned long long packsc(float s, unsigned col) {
    unsigned u = __float_as_uint(s);
    u ^= ((unsigned)(((int)u) >> 31)) | 0x80000000u;
    return ((unsigned long long)u << 32) | col;
}

// ---------------------------------------------------------------------------
// Kernel 0: init scratch
// ---------------------------------------------------------------------------
__global__ void vq_init_kernel() {
    int i = blockIdx.x * blockDim.x + threadIdx.x;
    int stride = gridDim.x * blockDim.x;
    for (size_t j = i; j < (size_t)Kv * Dv; j += stride) g_embed[j] = 0.f;
    for (int j = i; j < Kv; j += stride) g_counts[j] = 0.f;
    for (int j = i; j < Nv; j += stride) g_pack[j] = ~0ull;
    if (i == 0) { g_sumsq = 0.f; g_sum_ema = 0.f; }
}

// ---------------------------------------------------------------------------
// Kernel 1: codebook row squared norms
// ---------------------------------------------------------------------------
__global__ void vq_c2_kernel(const float* __restrict__ cb) {
    int k = blockIdx.x;
    int t = threadIdx.x;  // 128
    const float* r = cb + (size_t)k * Dv;
    float s = 0.f;
#pragma unroll
    for (int u = 0; u < 3; ++u) { float v = r[t + u * 128]; s = fmaf(v, v, s); }
#pragma unroll
    for (int o = 16; o; o >>= 1) s += __shfl_down_sync(0xffffffffu, s, o);
    __shared__ float ws[4];
    if ((t & 31) == 0) ws[t >> 5] = s;
    __syncthreads();
    if (t == 0) g_c2[k] = ws[0] + ws[1] + ws[2] + ws[3];
}

// ---------------------------------------------------------------------------
// Kernel 2: sum of ema_cluster_size
// ---------------------------------------------------------------------------
__global__ void vq_sumema_kernel(const float* __restrict__ ema_cs) {
    int t = threadIdx.x;  // 256
    float s = 0.f;
    for (int j = t; j < Kv; j += 256) s += ema_cs[j];
#pragma unroll
    for (int o = 16; o; o >>= 1) s += __shfl_down_sync(0xffffffffu, s, o);
    __shared__ float ws[8];
    if ((t & 31) == 0) ws[t >> 5] = s;
    __syncthreads();
    if (t == 0) {
        float r = 0.f;
#pragma unroll
        for (int w = 0; w < 8; ++w) r += ws[w];
        g_sum_ema = r;
    }
}

// ---------------------------------------------------------------------------
// Kernel 3: 3xTF32 mma.sync distance GEMM + argmin
//   CTA 256 threads (8 warps, 2 m x 4 n), CTA tile 128x128, warp tile 64x32
//   K chunks of 16 (two k8 steps), double-buffered fragment-major SMEM
// ---------------------------------------------------------------------------
#define KSPLIT 16
#define NTILES 4               // 512 codes per CTA / 128
#define NCHUNK (Dv / 16)       // 24 k16 chunks

// SMEM: fragment-major float4 packets (hi_c, hi_c+4, lo_c, lo_c+4)
//   A_pair[buf][k8][row(128)][kk(4)]   B_pair likewise with n instead of row
#define APAIR_IDX(buf, s2, row, kk) ((((buf)*2 + (s2)) * 128 + (row)) * 4 + (kk))
#define SM_A_F4 (2 * 2 * 128 * 4)     // 2048 float4 = 32KB
#define SM_B_F4 (2 * 2 * 128 * 4)
#define SMEM_DYN ((SM_A_F4 + SM_B_F4) * 16 + 128 * 8)

__device__ __forceinline__ void mma_tf32(float* c,
                                         uint32_t a0, uint32_t a1,
                                         uint32_t a2, uint32_t a3,
                                         uint32_t b0, uint32_t b1) {
    asm volatile(
        "mma.sync.aligned.m16n8k8.row.col.f32.tf32.tf32.f32 "
        "{%0,%1,%2,%3}, {%4,%5,%6,%7}, {%8,%9}, {%0,%1,%2,%3};"
        : "+f"(c[0]), "+f"(c[1]), "+f"(c[2]), "+f"(c[3])
        : "r"(a0), "r"(a1), "r"(a2), "r"(a3), "r"(b0), "r"(b1));
}

__device__ __forceinline__ void split_tf32(float x, uint32_t& hi, uint32_t& lo) {
    uint32_t u = __float_as_uint(x);
    hi = u & 0xFFFFE000u;
    float lf = x - __uint_as_float(hi);
    lo = __float_as_uint(lf) & 0xFFFFE000u;
}

extern __shared__ float4 dynf4[];

__global__ void __launch_bounds__(256)
vq_mma_argmin(const float* __restrict__ z, const float* __restrict__ cb) {
    float4* As = dynf4;                       // SM_A_F4
    float4* Bsm = dynf4 + SM_A_F4;            // SM_B_F4
    unsigned long long* rbest =
        (unsigned long long*)(dynf4 + SM_A_F4 + SM_B_F4);  // [128]

    const int tid = threadIdx.x;
    const int lane = tid & 31;
    const int wid = tid >> 5;
    const int wm = wid & 1;       // warp m position (0..1)
    const int wn = wid >> 1;      // warp n position (0..3)
    const int row0 = blockIdx.x * 128;
    const int kbase = blockIdx.y * (Kv / KSPLIT);   // 512-code range

    if (tid < 128) rbest[tid] = ~0ull;
    __syncthreads();

    // producer indexing: each thread owns (row = tid>>1, k8 half = tid&1)
    const int prow = tid >> 1;
    const int ps2 = tid & 1;
    const float* zsrc = z + (size_t)(row0 + prow) * Dv + ps2 * 8;

    for (int ntile = 0; ntile < NTILES; ++ntile) {
        const int nbase = kbase + ntile * 128;
        const float* bsrc = cb + (size_t)(nbase + prow) * Dv + ps2 * 8;

        auto load_chunk = [&](int buf, int ch) {
            // A: 8 floats (k offsets ch*16 + ps2*8 .. +7)
            const float4 a0 = *(const float4*)(zsrc + ch * 16);
            const float4 a1 = *(const float4*)(zsrc + ch * 16 + 4);
            float av[8] = {a0.x, a0.y, a0.z, a0.w, a1.x, a1.y, a1.z, a1.w};
            uint32_t hi[8], lo[8];
#pragma unroll
            for (int i = 0; i < 8; ++i) split_tf32(av[i], hi[i], lo[i]);
#pragma unroll
            for (int kk = 0; kk < 4; ++kk) {
                float4 p;
                p.x = __uint_as_float(hi[kk]);
                p.y = __uint_as_float(hi[kk + 4]);
                p.z = __uint_as_float(lo[kk]);
                p.w = __uint_as_float(lo[kk + 4]);
                As[APAIR_IDX(buf, ps2, prow, kk)] = p;
            }
            // B: same for codebook rows
            const float4 b0 = *(const float4*)(bsrc + ch * 16);
            const float4 b1 = *(const float4*)(bsrc + ch * 16 + 4);
            float bv[8] = {b0.x, b0.y, b0.z, b0.w, b1.x, b1.y, b1.z, b1.w};
#pragma unroll
            for (int i = 0; i < 8; ++i) split_tf32(bv[i], hi[i], lo[i]);
#pragma unroll
            for (int kk = 0; kk < 4; ++kk) {
                float4 p;
                p.x = __uint_as_float(hi[kk]);
                p.y = __uint_as_float(hi[kk + 4]);
                p.z = __uint_as_float(lo[kk]);
                p.w = __uint_as_float(lo[kk + 4]);
                Bsm[APAIR_IDX(buf, ps2, prow, kk)] = p;
            }
        };

        float acc[4][4][4];
#pragma unroll
        for (int mt = 0; mt < 4; ++mt)
#pragma unroll
            for (int nt = 0; nt < 4; ++nt)
#pragma unroll
                for (int q = 0; q < 4; ++q) acc[mt][nt][q] = 0.f;

        load_chunk(0, 0);
        __syncthreads();
        int buf = 0;

        for (int ch = 0; ch < NCHUNK; ++ch) {
            if (ch + 1 < NCHUNK) load_chunk(buf ^ 1, ch + 1);

#pragma unroll
            for (int s2 = 0; s2 < 2; ++s2) {
                // A fragments (hi and lo) via 2 LDS.128 per mtile
                uint32_t ahi[4][4], alo[4][4];
#pragma unroll
                for (int mt = 0; mt < 4; ++mt) {
                    int r = (lane >> 2) + mt * 16 + wm * 64;
                    float4 p = As[APAIR_IDX(buf, s2, r, lane & 3)];
                    float4 q = As[APAIR_IDX(buf, s2, r + 8, lane & 3)];
                    ahi[mt][0] = __float_as_uint(p.x);
                    ahi[mt][1] = __float_as_uint(q.x);
                    ahi[mt][2] = __float_as_uint(p.y);
                    ahi[mt][3] = __float_as_uint(q.y);
                    alo[mt][0] = __float_as_uint(p.z);
                    alo[mt][1] = __float_as_uint(q.z);
                    alo[mt][2] = __float_as_uint(p.w);
                    alo[mt][3] = __float_as_uint(q.w);
                }
                uint32_t bhi[4][2], blo[4][2];
#pragma unroll
                for (int nt = 0; nt < 4; ++nt) {
                    int n = (lane >> 2) + nt * 8 + wn * 32;
                    float4 p = Bsm[APAIR_IDX(buf, s2, n, lane & 3)];
                    bhi[nt][0] = __float_as_uint(p.x);
                    bhi[nt][1] = __float_as_uint(p.y);
                    blo[nt][0] = __float_as_uint(p.z);
                    blo[nt][1] = __float_as_uint(p.w);
                }
#pragma unroll
                for (int mt = 0; mt < 4; ++mt)
#pragma unroll
                    for (int nt = 0; nt < 4; ++nt) {
                        mma_tf32(acc[mt][nt], ahi[mt][0], ahi[mt][1],
                                 ahi[mt][2], ahi[mt][3], bhi[nt][0], bhi[nt][1]);
                        mma_tf32(acc[mt][nt], ahi[mt][0], ahi[mt][1],
                                 ahi[mt][2], ahi[mt][3], blo[nt][0], blo[nt][1]);
                        mma_tf32(acc[mt][nt], alo[mt][0], alo[mt][1],
                                 alo[mt][2], alo[mt][3], bhi[nt][0], bhi[nt][1]);
                    }
            }
            __syncthreads();
            buf ^= 1;
        }

        // ---- epilogue: score = ||c||^2 - 2*dot ; argmin ----
#pragma unroll
        for (int mt = 0; mt < 4; ++mt) {
            int r0l = (lane >> 2) + mt * 16 + wm * 64;   // local rows r0l, r0l+8
            unsigned long long bst0 = ~0ull, bst1 = ~0ull;
#pragma unroll
            for (int nt = 0; nt < 4; ++nt) {
                unsigned gcol = (unsigned)(nbase + nt * 8 + wn * 32 + 2 * (lane & 3));
                float c2a = __ldg(&g_c2[gcol]);
                float c2b = __ldg(&g_c2[gcol + 1]);
                unsigned long long p;
                p = packsc(fmaf(-2.f, acc[mt][nt][0], c2a), gcol);
                if (p < bst0) bst0 = p;
                p = packsc(fmaf(-2.f, acc[mt][nt][1], c2b), gcol + 1);
                if (p < bst0) bst0 = p;
                p = packsc(fmaf(-2.f, acc[mt][nt][2], c2a), gcol);
                if (p < bst1) bst1 = p;
                p = packsc(fmaf(-2.f, acc[mt][nt][3], c2b), gcol + 1);
                if (p < bst1) bst1 = p;
            }
            // reduce over the 4 lanes of the quad (same rows, different cols)
#pragma unroll
            for (int off = 1; off <= 2; off <<= 1) {
                unsigned long long o0 = __shfl_xor_sync(0xffffffffu, bst0, off);
                unsigned long long o1 = __shfl_xor_sync(0xffffffffu, bst1, off);
                if (o0 < bst0) bst0 = o0;
                if (o1 < bst1) bst1 = o1;
            }
            if ((lane & 3) == 0) {
                atomicMin(&rbest[r0l], bst0);
                atomicMin(&rbest[r0l + 8], bst1);
            }
        }
        __syncthreads();   // rbest updates done; SMEM reuse safe next ntile
    }

    if (tid < 128) atomicMin(&g_pack[row0 + tid], rbest[tid]);
}

// ---------------------------------------------------------------------------
// Kernel 4: gather quantized, straight-through, loss partial, EMA scatter
// ---------------------------------------------------------------------------
__global__ void vq_gather_kernel(const float* __restrict__ z,
                                 const float* __restrict__ cb,
                                 float* __restrict__ out,
                                 long long out_size) {
    int n = blockIdx.x;
    int t = threadIdx.x;  // 128
    int idx = (int)(g_pack[n] & 0xffffffffull);
    const float* zr = z + (size_t)n * Dv;
    const float* cr = cb + (size_t)idx * Dv;
    float ss = 0.f;
#pragma unroll
    for (int u = 0; u < 3; ++u) {
        int d = t + u * 128;
        float zv = zr[d];
        float q = cr[d];
        out[OFF_Q + (size_t)n * Dv + d] = zv + (q - zv);
        float df = zv - q;
        ss = fmaf(df, df, ss);
        atomicAdd(&g_embed[(size_t)idx * Dv + d], zv);
    }
#pragma unroll
    for (int o = 16; o; o >>= 1) ss += __shfl_down_sync(0xffffffffu, ss, o);
    __shared__ float ws[4];
    if ((t & 31) == 0) ws[t >> 5] = ss;
    __syncthreads();
    if (t == 0) {
        atomicAdd(&g_sumsq, ws[0] + ws[1] + ws[2] + ws[3]);
        atomicAdd(&g_counts[idx], 1.0f);
        if (out_size > (long long)OFF_IDX) out[OFF_IDX + n] = (float)idx;
    }
}

// ---------------------------------------------------------------------------
// Kernel 5: finalize EMA outputs + loss
// ---------------------------------------------------------------------------
__global__ void vq_finalize_kernel(const float* __restrict__ ema_cs,
                                   const float* __restrict__ ema_es,
                                   float* __restrict__ out,
                                   long long out_size) {
    int k = blockIdx.x;
    int t = threadIdx.x;  // 128
    float nn = 0.99f * g_sum_ema + 0.01f * (float)Nv;
    float ncs = 0.99f * ema_cs[k] + 0.01f * g_counts[k];
    float smoothed = (ncs + 1e-5f) / (nn + (float)Kv * 1e-5f) * nn;
    if (t == 0 && out_size > (long long)OFF_NCS) out[OFF_NCS + k] = ncs;
    if (t == 0 && k == 0 && out_size > (long long)OFF_LOSS)
        out[OFF_LOSS] = 1.25f * g_sumsq / (float)((size_t)Nv * Dv);
    if (out_size > (long long)OFF_NES) {
#pragma unroll
        for (int u = 0; u < 3; ++u) {
            int d = t + u * 128;
            size_t o = (size_t)k * Dv + d;
            float nes = 0.99f * ema_es[o] + 0.01f * g_embed[o];
            out[OFF_NES + o] = nes;
            out[OFF_NCB + o] = nes / smoothed;
        }
    }
}

// ---------------------------------------------------------------------------
extern "C" void kernel_launch(void* const* d_in, const int* in_sizes, int n_in,
                              void* d_out, int out_size) {
    const float* z       = (const float*)d_in[0];
    const float* cb      = (const float*)d_in[1];
    const float* ema_cs  = (const float*)d_in[2];
    const float* ema_es  = (const float*)d_in[3];
    float* out = (float*)d_out;
    (void)in_sizes; (void)n_in;

    static int attr_done = 0;
    if (!attr_done) {
        cudaFuncSetAttribute(vq_mma_argmin,
                             cudaFuncAttributeMaxDynamicSharedMemorySize,
                             SMEM_DYN);
        attr_done = 1;
    }

    vq_init_kernel<<<2048, 256>>>();
    vq_c2_kernel<<<Kv, 128>>>(cb);
    vq_sumema_kernel<<<1, 256>>>(ema_cs);
    vq_mma_argmin<<<dim3(Nv / 128, KSPLIT), 256, SMEM_DYN>>>(z, cb);
    vq_gather_kernel<<<Nv, 128>>>(z, cb, out, (long long)out_size);
    vq_finalize_kernel<<<Kv, 128>>>(ema_cs, ema_es, out, (long long)out_size);
}